// round 9
// baseline (speedup 1.0000x reference)
#include <cuda_runtime.h>

// EMA over the innermost frames axis.
// input:         (16, 8, 256, 2048) fp32, frames contiguous
// initial_state: (16, 8, 256)       fp32
// weight:        (8, 256)           fp32   (clamped to [0,1])
// out:           (16, 8, 256, 2048) fp32
//
// Two rows per warp (independent carry chains interleaved in the issue
// stream -> halves effective serial SHFL/FMA latency per byte; R2/R6
// plateaued at DRAM=80%, issue=22% on a single chain). Lane -> contiguous
// float4 (perfect coalescing), depth-1 pair prefetch, streaming hints.
// Unroll capped at 4 to keep the binary small.

#define EMA_N_FRAMES 2048
#define EMA_CHUNKS   (EMA_N_FRAMES / 128)   // 16 chunks of 128 frames
#define EMA_WARPS_PER_BLOCK 8
#define EMA_THREADS (EMA_WARPS_PER_BLOCK * 32)

struct EmaCoef {
    float w, a, a2, a3, a4, a_chunk, a4_lane;
};

__device__ __forceinline__ void make_coef(EmaCoef& k, float w_raw, int lane) {
    float w = fminf(fmaxf(w_raw, 0.0f), 1.0f);
    k.w  = w;
    k.a  = 1.0f - w;
    k.a2 = k.a * k.a;
    k.a3 = k.a2 * k.a;
    k.a4 = k.a2 * k.a2;
    float a8   = k.a4 * k.a4;
    float a16  = a8   * a8;
    float a32  = a16  * a16;
    float a64  = a32  * a32;
    k.a_chunk  = a64  * a64;          // a^128
    float p = k.a4, r = 1.0f;
    int e = lane;
    while (e) { if (e & 1) r *= p; p *= p; e >>= 1; }
    k.a4_lane = r;
}

__global__ __launch_bounds__(EMA_THREADS)
void ema_scan_kernel(const float* __restrict__ x,
                     const float* __restrict__ y0,
                     const float* __restrict__ wgt,
                     float* __restrict__ out,
                     int n_rows, int wgt_mod) {
    const int warp = blockIdx.x * EMA_WARPS_PER_BLOCK + (threadIdx.x >> 5);
    const int row0 = warp * 2;
    if (row0 >= n_rows) return;               // n_rows even; whole warps only
    const int lane = threadIdx.x & 31;

    EmaCoef kA, kB;
    make_coef(kA, wgt[row0 % wgt_mod], lane);
    make_coef(kB, wgt[(row0 + 1) % wgt_mod], lane);

    const float4* __restrict__ xA =
        reinterpret_cast<const float4*>(x + (size_t)row0 * EMA_N_FRAMES);
    const float4* __restrict__ xB =
        reinterpret_cast<const float4*>(x + (size_t)(row0 + 1) * EMA_N_FRAMES);
    float4* __restrict__ yA =
        reinterpret_cast<float4*>(out + (size_t)row0 * EMA_N_FRAMES);
    float4* __restrict__ yB =
        reinterpret_cast<float4*>(out + (size_t)(row0 + 1) * EMA_N_FRAMES);

    float carryA = y0[row0];
    float carryB = y0[row0 + 1];

    // depth-1 pair prefetch: one chunk of each row in flight
    float4 bufA = __ldcs(&xA[lane]);
    float4 bufB = __ldcs(&xB[lane]);

    #pragma unroll 4
    for (int c = 0; c < EMA_CHUNKS; ++c) {
        float4 nA = make_float4(0.f, 0.f, 0.f, 0.f);
        float4 nB = make_float4(0.f, 0.f, 0.f, 0.f);
        if (c + 1 < EMA_CHUNKS) {
            nA = __ldcs(&xA[(c + 1) * 32 + lane]);
            nB = __ldcs(&xB[(c + 1) * 32 + lane]);
        }

        // --- interleaved serial 4-element recurrences (independent chains) ---
        float tA0 = kA.w * bufA.x;
        float tB0 = kB.w * bufB.x;
        float tA1 = fmaf(kA.a, tA0, kA.w * bufA.y);
        float tB1 = fmaf(kB.a, tB0, kB.w * bufB.y);
        float tA2 = fmaf(kA.a, tA1, kA.w * bufA.z);
        float tB2 = fmaf(kB.a, tB1, kB.w * bufB.z);
        float tA3 = fmaf(kA.a, tA2, kA.w * bufA.w);
        float tB3 = fmaf(kB.a, tB2, kB.w * bufB.w);

        // --- interleaved inclusive warp scans (decay a^4 per segment) ---
        float sA = tA3, sB = tB3;
        float pwA = kA.a4, pwB = kB.a4;
        #pragma unroll
        for (int off = 1; off < 32; off <<= 1) {
            float upA = __shfl_up_sync(0xffffffffu, sA, off);
            float upB = __shfl_up_sync(0xffffffffu, sB, off);
            if (lane >= off) {
                sA = fmaf(pwA, upA, sA);
                sB = fmaf(pwB, upB, sB);
            }
            pwA = pwA * pwA;
            pwB = pwB * pwB;
        }

        float exA = __shfl_up_sync(0xffffffffu, sA, 1);
        float exB = __shfl_up_sync(0xffffffffu, sB, 1);
        float prA = (lane == 0) ? carryA : fmaf(kA.a4_lane, carryA, exA);
        float prB = (lane == 0) ? carryB : fmaf(kB.a4_lane, carryB, exB);

        float4 oA, oB;
        oA.x = fmaf(kA.a,  prA, tA0);
        oB.x = fmaf(kB.a,  prB, tB0);
        oA.y = fmaf(kA.a2, prA, tA1);
        oB.y = fmaf(kB.a2, prB, tB1);
        oA.z = fmaf(kA.a3, prA, tA2);
        oB.z = fmaf(kB.a3, prB, tB2);
        oA.w = fmaf(kA.a4, prA, tA3);
        oB.w = fmaf(kB.a4, prB, tB3);
        __stcs(&yA[c * 32 + lane], oA);
        __stcs(&yB[c * 32 + lane], oB);

        float sA31 = __shfl_sync(0xffffffffu, sA, 31);
        float sB31 = __shfl_sync(0xffffffffu, sB, 31);
        carryA = fmaf(kA.a_chunk, carryA, sA31);
        carryB = fmaf(kB.a_chunk, carryB, sB31);

        bufA = nA;
        bufB = nB;
    }
}

extern "C" void kernel_launch(void* const* d_in, const int* in_sizes, int n_in,
                              void* d_out, int out_size) {
    const float* x   = (const float*)d_in[0];   // input  (B, R, N, F)
    const float* y0  = (const float*)d_in[1];   // initial_state (B, R, N)
    const float* wgt = (const float*)d_in[2];   // weight (R, N)
    float* out = (float*)d_out;

    const int n_rows  = in_sizes[1];            // B*R*N = 32768 rows
    const int wgt_mod = in_sizes[2];            // R*N   = 2048

    const int n_warps = n_rows / 2;             // two rows per warp
    const int blocks  = (n_warps + EMA_WARPS_PER_BLOCK - 1) / EMA_WARPS_PER_BLOCK;
    ema_scan_kernel<<<blocks, EMA_THREADS>>>(x, y0, wgt, out, n_rows, wgt_mod);
}